// round 9
// baseline (speedup 1.0000x reference)
#include <cuda_runtime.h>
#include <cstdint>

#define SEQ   2048
#define NH    16
#define DKH   64
#define BATCH 4
#define DM    1024

// Scratch (allocation-free) — referenced ONLY from device code
__device__ float g_qkv[3ULL * BATCH * NH * SEQ * DKH];            // 96 MB
__device__ float g_att[(size_t)BATCH * SEQ * DM];                 // 32 MB (tf32-rounded)
__device__ float g_xr [(size_t)BATCH * SEQ * DM];                 // 32 MB (tf32-rounded x)
__device__ float g_WT [(size_t)3072 * 1024 + (size_t)1024 * 1024];// W^T (tf32-rounded)

// ---------------------------------------------------------------------------
// helpers
// ---------------------------------------------------------------------------
static __device__ __forceinline__ uint32_t smem_u32(const void* p) {
    uint32_t a;
    asm("{ .reg .u64 t; cvta.to.shared.u64 t, %1; cvt.u32.u64 %0, t; }" : "=r"(a) : "l"(p));
    return a;
}
static __device__ __forceinline__ uint32_t f2tf32(float x) {
    uint32_t r; asm("cvt.rna.tf32.f32 %0, %1;" : "=r"(r) : "f"(x)); return r;
}

#define MMA_TF32(d, a, b)                                                        \
    asm volatile("mma.sync.aligned.m16n8k8.row.col.f32.tf32.tf32.f32 "           \
        "{%0,%1,%2,%3}, {%4,%5,%6,%7}, {%8,%9}, {%0,%1,%2,%3};"                  \
        : "+f"((d)[0]), "+f"((d)[1]), "+f"((d)[2]), "+f"((d)[3])                 \
        : "r"((a)[0]), "r"((a)[1]), "r"((a)[2]), "r"((a)[3]),                     \
          "r"((b)[0]), "r"((b)[1]))

#define CP_ASYNC16(dst, src)                                                     \
    asm volatile("cp.async.cg.shared.global [%0], [%1], 16;" :: "r"(dst), "l"(src))
#define CP_COMMIT()  asm volatile("cp.async.commit_group;" ::: "memory")
#define CP_WAIT1()   asm volatile("cp.async.wait_group 1;" ::: "memory")

// ---------------------------------------------------------------------------
// Weight transpose + RNA-round to tf32: g_WT[off + n*1024 + k] = rna(W[k*N+n])
// ---------------------------------------------------------------------------
__global__ __launch_bounds__(256) void transpose_rna(const float* __restrict__ W,
                                                     int N, size_t out_off)
{
    __shared__ float t[32][33];
    const int tx = threadIdx.x, ty = threadIdx.y;
    const int n0 = blockIdx.x * 32, k0 = blockIdx.y * 32;
    #pragma unroll
    for (int i = 0; i < 4; ++i)
        t[ty + i * 8][tx] = W[(size_t)(k0 + ty + i * 8) * N + n0 + tx];
    __syncthreads();
    float* WT = g_WT + out_off;
    #pragma unroll
    for (int i = 0; i < 4; ++i)
        WT[(size_t)(n0 + ty + i * 8) * 1024 + k0 + tx] =
            __uint_as_float(f2tf32(t[tx][ty + i * 8]));
}

// RNA-round x into g_xr (float4 per thread)
__global__ __launch_bounds__(256) void round_x(const float* __restrict__ in)
{
    const size_t i = ((size_t)blockIdx.x * 256 + threadIdx.x) * 4;
    const float4 v = *(const float4*)&in[i];
    uint4 r;
    r.x = f2tf32(v.x); r.y = f2tf32(v.y); r.z = f2tf32(v.z); r.w = f2tf32(v.w);
    *(uint4*)&g_xr[i] = r;
}

// ---------------------------------------------------------------------------
// tf32 mma.sync GEMM: C[128,128] per CTA, K=1024 in 32-wide stages, 3-stage
// cp.async pipeline. 4 warps (2x2), warp tile 64x64 (4 mfrag x 8 nfrag).
// Pointers to scratch resolved IN-KERNEL (device symbols are invalid on host).
// QKV=true : A=g_xr, B=g_WT,          scatter into g_qkv with bias.
// QKV=false: A=g_att, B=g_WT+3M,      write Cout with bias.
// ---------------------------------------------------------------------------
#define STG_BYTES 36864                 // per stage: A 128*36*4 + B same
#define A_FLOATS  4608                  // 18432/4

template<int N, bool QKV>
__global__ __launch_bounds__(128) void gemm_mma(const float* __restrict__ bias,
                                                float* __restrict__ Cout)
{
    extern __shared__ char sm[];
    const float* __restrict__ Aptr = QKV ? g_xr : g_att;
    const float* __restrict__ Bt   = QKV ? g_WT : (g_WT + (size_t)3072 * 1024);

    const int tid  = threadIdx.x;
    const int lane = tid & 31, wid = tid >> 5;
    const int wm   = wid >> 1, wn = wid & 1;
    const int gp   = lane >> 2, tg = lane & 3;
    const int m0   = blockIdx.y * 128, n0 = blockIdx.x * 128;
    const uint32_t smb = smem_u32(sm);

    float d[4][8][4];
    #pragma unroll
    for (int mf = 0; mf < 4; ++mf)
        #pragma unroll
        for (int nf = 0; nf < 8; ++nf)
            #pragma unroll
            for (int q = 0; q < 4; ++q) d[mf][nf][q] = 0.f;

    // loader: f = i*128+tid -> row r=f>>3 (0..127), 16B-chunk kq=f&7
    const int lr = tid >> 3, lkq = tid & 7;

    auto load_stage = [&](int s, int k0) {
        const uint32_t ab = smb + s * STG_BYTES;
        #pragma unroll
        for (int i = 0; i < 8; ++i) {
            const int r = lr + i * 16;
            const uint32_t off = (uint32_t)(r * 36 + lkq * 4) * 4;
            CP_ASYNC16(ab + off,         Aptr + (size_t)(m0 + r) * 1024 + k0 + lkq * 4);
            CP_ASYNC16(ab + 18432 + off, Bt   + (size_t)(n0 + r) * 1024 + k0 + lkq * 4);
        }
    };

    load_stage(0, 0);  CP_COMMIT();
    load_stage(1, 32); CP_COMMIT();

    for (int t = 0; t < 32; ++t) {
        CP_WAIT1();
        __syncthreads();
        if (t + 2 < 32) load_stage((t + 2) % 3, (t + 2) * 32);
        CP_COMMIT();

        const uint32_t* As_ = (const uint32_t*)(sm + (t % 3) * STG_BYTES);
        const uint32_t* Bs_ = As_ + A_FLOATS;

        #pragma unroll
        for (int kk = 0; kk < 32; kk += 8) {
            uint32_t afr[4][4], bfr[8][2];
            #pragma unroll
            for (int mf = 0; mf < 4; ++mf) {
                const int r0 = (wm * 64 + mf * 16 + gp) * 36 + kk + tg;
                afr[mf][0] = As_[r0];
                afr[mf][1] = As_[r0 + 8 * 36];
                afr[mf][2] = As_[r0 + 4];
                afr[mf][3] = As_[r0 + 8 * 36 + 4];
            }
            #pragma unroll
            for (int nf = 0; nf < 8; ++nf) {
                const int c0 = (wn * 64 + nf * 8 + gp) * 36 + kk + tg;
                bfr[nf][0] = Bs_[c0];
                bfr[nf][1] = Bs_[c0 + 4];
            }
            #pragma unroll
            for (int mf = 0; mf < 4; ++mf)
                #pragma unroll
                for (int nf = 0; nf < 8; ++nf)
                    MMA_TF32(d[mf][nf], afr[mf], bfr[nf]);
        }
    }

    // epilogue: c0,c1 at (row, col..col+1); c2,c3 at (row+8, ...)
    #pragma unroll
    for (int mf = 0; mf < 4; ++mf) {
        const int row = m0 + wm * 64 + mf * 16 + gp;
        #pragma unroll
        for (int nf = 0; nf < 8; ++nf) {
            const int col = n0 + wn * 64 + nf * 8 + 2 * tg;
            const float2 bv = *(const float2*)&bias[col];
            #pragma unroll
            for (int h = 0; h < 2; ++h) {
                const int r = row + h * 8;
                float2 v;
                v.x = d[mf][nf][2 * h + 0] + bv.x;
                v.y = d[mf][nf][2 * h + 1] + bv.y;
                if (QKV) {
                    const int which = col >> 10, dd = col & 1023;
                    const int hh = dd >> 6, dk = dd & 63;
                    const int bb = r >> 11, ss = r & 2047;
                    *(float2*)&g_qkv[((size_t)(which * 64 + bb * 16 + hh) * SEQ + ss) * DKH + dk] = v;
                } else {
                    *(float2*)&Cout[(size_t)r * DM + col] = v;
                }
            }
        }
    }
}

// ---------------------------------------------------------------------------
// Causal flash attention, fp32 (epilogue stores tf32-rounded for proj-A)
// ---------------------------------------------------------------------------
__global__ __launch_bounds__(256) void attn_kernel()
{
    extern __shared__ __align__(16) float smbuf[];
    float* Qs  = smbuf;
    float* KPs = smbuf + 64 * 68;
    float* Vs  = smbuf + 2 * 64 * 68;

    const int tid = threadIdx.x;
    const int ty  = tid >> 4;
    const int tx  = tid & 15;
    const int qi  = (int)gridDim.x - 1 - (int)blockIdx.x;
    const int bh  = blockIdx.y;

    const float* Qg = g_qkv + (size_t)(bh)       * (SEQ * DKH);
    const float* Kg = g_qkv + (size_t)(64 + bh)  * (SEQ * DKH);
    const float* Vg = g_qkv + (size_t)(128 + bh) * (SEQ * DKH);

    #pragma unroll
    for (int it = 0; it < 4; ++it) {
        const int f = it * 256 + tid;
        const int r = f >> 4;
        const int c = (f & 15) * 4;
        const float4 q4 = *(const float4*)&Qg[(size_t)(qi * 64 + r) * 64 + c];
        Qs[(c + 0) * 68 + r] = q4.x * 0.125f;
        Qs[(c + 1) * 68 + r] = q4.y * 0.125f;
        Qs[(c + 2) * 68 + r] = q4.z * 0.125f;
        Qs[(c + 3) * 68 + r] = q4.w * 0.125f;
    }

    float m[4], l[4], o[4][4];
    #pragma unroll
    for (int i = 0; i < 4; ++i) {
        m[i] = -1e30f; l[i] = 0.f;
        #pragma unroll
        for (int j = 0; j < 4; ++j) o[i][j] = 0.f;
    }

    for (int j = 0; j <= qi; ++j) {
        #pragma unroll
        for (int it = 0; it < 4; ++it) {
            const int f = it * 256 + tid;
            const int r = f >> 4;
            const int c = (f & 15) * 4;
            const size_t g = (size_t)(j * 64 + r) * 64 + c;
            const float4 k4 = *(const float4*)&Kg[g];
            KPs[(c + 0) * 68 + r] = k4.x;
            KPs[(c + 1) * 68 + r] = k4.y;
            KPs[(c + 2) * 68 + r] = k4.z;
            KPs[(c + 3) * 68 + r] = k4.w;
            *(float4*)&Vs[r * 68 + c] = *(const float4*)&Vg[g];
        }
        __syncthreads();

        float s[4][4];
        #pragma unroll
        for (int i = 0; i < 4; ++i)
            #pragma unroll
            for (int c = 0; c < 4; ++c) s[i][c] = 0.f;
        #pragma unroll 16
        for (int k = 0; k < 64; ++k) {
            const float4 qa = *(const float4*)&Qs [k * 68 + ty * 4];
            const float4 kb = *(const float4*)&KPs[k * 68 + tx * 4];
            const float qv[4] = {qa.x, qa.y, qa.z, qa.w};
            const float kv[4] = {kb.x, kb.y, kb.z, kb.w};
            #pragma unroll
            for (int i = 0; i < 4; ++i)
                #pragma unroll
                for (int c = 0; c < 4; ++c)
                    s[i][c] = fmaf(qv[i], kv[c], s[i][c]);
        }

        if (j == qi) {
            #pragma unroll
            for (int i = 0; i < 4; ++i)
                #pragma unroll
                for (int c = 0; c < 4; ++c)
                    if (tx * 4 + c > ty * 4 + i) s[i][c] = -1e30f;
        }
        __syncthreads();

        #pragma unroll
        for (int i = 0; i < 4; ++i) {
            float mt = fmaxf(fmaxf(s[i][0], s[i][1]), fmaxf(s[i][2], s[i][3]));
            #pragma unroll
            for (int off = 8; off > 0; off >>= 1)
                mt = fmaxf(mt, __shfl_xor_sync(0xffffffffu, mt, off));
            const float mnew = fmaxf(m[i], mt);
            const float corr = __expf(m[i] - mnew);
            float rs = 0.f;
            #pragma unroll
            for (int c = 0; c < 4; ++c) {
                s[i][c] = __expf(s[i][c] - mnew);
                rs += s[i][c];
            }
            #pragma unroll
            for (int off = 8; off > 0; off >>= 1)
                rs += __shfl_xor_sync(0xffffffffu, rs, off);
            l[i] = l[i] * corr + rs;
            m[i] = mnew;
            #pragma unroll
            for (int c = 0; c < 4; ++c) o[i][c] *= corr;
            #pragma unroll
            for (int c = 0; c < 4; ++c)
                KPs[(tx * 4 + c) * 68 + ty * 4 + i] = s[i][c];
        }
        __syncthreads();

        #pragma unroll 16
        for (int k = 0; k < 64; ++k) {
            const float4 p4 = *(const float4*)&KPs[k * 68 + ty * 4];
            const float4 v4 = *(const float4*)&Vs [k * 68 + tx * 4];
            const float pv[4] = {p4.x, p4.y, p4.z, p4.w};
            const float vv[4] = {v4.x, v4.y, v4.z, v4.w};
            #pragma unroll
            for (int i = 0; i < 4; ++i)
                #pragma unroll
                for (int c = 0; c < 4; ++c)
                    o[i][c] = fmaf(pv[i], vv[c], o[i][c]);
        }
        __syncthreads();
    }

    const int bb = bh >> 4, hh = bh & 15;
    #pragma unroll
    for (int i = 0; i < 4; ++i) {
        const float inv = 1.0f / l[i];
        const int srow = qi * 64 + ty * 4 + i;
        uint4 v;   // store tf32-rounded (input to tensor-core proj GEMM)
        v.x = f2tf32(o[i][0] * inv); v.y = f2tf32(o[i][1] * inv);
        v.z = f2tf32(o[i][2] * inv); v.w = f2tf32(o[i][3] * inv);
        *(uint4*)&g_att[((size_t)bb * SEQ + srow) * DM + hh * 64 + tx * 4] = v;
    }
}

// ---------------------------------------------------------------------------
extern "C" void kernel_launch(void* const* d_in, const int* in_sizes, int n_in,
                              void* d_out, int out_size)
{
    const float* x    = (const float*)d_in[0];
    const float* Wqkv = (const float*)d_in[1];
    const float* bqkv = (const float*)d_in[2];
    const float* Wo   = (const float*)d_in[3];
    const float* bo   = (const float*)d_in[4];
    float* out = (float*)d_out;

    // 0) pre-round inputs to tf32 (RNA — avoids HMMA truncation bias)
    transpose_rna<<<dim3(96, 32), dim3(32, 8)>>>(Wqkv, 3072, 0);
    transpose_rna<<<dim3(32, 32), dim3(32, 8)>>>(Wo, 1024, (size_t)3072 * 1024);
    round_x<<<8192, 256>>>(x);

    const int gsm = 3 * STG_BYTES;   // 110592
    cudaFuncSetAttribute(gemm_mma<3072, true>,
                         cudaFuncAttributeMaxDynamicSharedMemorySize, gsm);
    cudaFuncSetAttribute(gemm_mma<1024, false>,
                         cudaFuncAttributeMaxDynamicSharedMemorySize, gsm);

    // 1) QKV projection (tf32 mma.sync) + bias, scatter head-major
    gemm_mma<3072, true><<<dim3(24, 64), 128, gsm>>>(bqkv, nullptr);

    // 2) causal flash attention (fp32 compute, tf32-rounded store)
    const int asm_sz = 3 * 64 * 68 * (int)sizeof(float);
    cudaFuncSetAttribute(attn_kernel, cudaFuncAttributeMaxDynamicSharedMemorySize, asm_sz);
    attn_kernel<<<dim3(32, BATCH * NH), 256, asm_sz>>>();

    // 3) output projection (tf32 mma.sync) + bias
    gemm_mma<1024, false><<<dim3(8, 64), 128, gsm>>>(bo, out);
}

// round 10
// speedup vs baseline: 1.0089x; 1.0089x over previous
#include <cuda_runtime.h>
#include <cstdint>

#define SEQ   2048
#define NH    16
#define DKH   64
#define BATCH 4
#define DM    1024

// Scratch (allocation-free) — referenced ONLY from device code
__device__ float g_qkv[3ULL * BATCH * NH * SEQ * DKH];            // 96 MB
__device__ float g_att[(size_t)BATCH * SEQ * DM];                 // 32 MB (tf32-rounded)
__device__ float g_xr [(size_t)BATCH * SEQ * DM];                 // 32 MB (tf32-rounded x)
__device__ float g_WT [(size_t)3072 * 1024 + (size_t)1024 * 1024];// W^T (tf32-rounded)

// ---------------------------------------------------------------------------
// helpers
// ---------------------------------------------------------------------------
static __device__ __forceinline__ uint32_t smem_u32(const void* p) {
    uint32_t a;
    asm("{ .reg .u64 t; cvta.to.shared.u64 t, %1; cvt.u32.u64 %0, t; }" : "=r"(a) : "l"(p));
    return a;
}
static __device__ __forceinline__ uint32_t f2tf32(float x) {
    uint32_t r; asm("cvt.rna.tf32.f32 %0, %1;" : "=r"(r) : "f"(x)); return r;
}

#define MMA_TF32(d, a, b)                                                        \
    asm volatile("mma.sync.aligned.m16n8k8.row.col.f32.tf32.tf32.f32 "           \
        "{%0,%1,%2,%3}, {%4,%5,%6,%7}, {%8,%9}, {%0,%1,%2,%3};"                  \
        : "+f"((d)[0]), "+f"((d)[1]), "+f"((d)[2]), "+f"((d)[3])                 \
        : "r"((a)[0]), "r"((a)[1]), "r"((a)[2]), "r"((a)[3]),                     \
          "r"((b)[0]), "r"((b)[1]))

#define CP_ASYNC16(dst, src)                                                     \
    asm volatile("cp.async.cg.shared.global [%0], [%1], 16;" :: "r"(dst), "l"(src))
#define CP_COMMIT()  asm volatile("cp.async.commit_group;" ::: "memory")
#define CP_WAIT1()   asm volatile("cp.async.wait_group 1;" ::: "memory")

// ---------------------------------------------------------------------------
// Weight transpose + RNA-round to tf32: g_WT[off + n*1024 + k] = rna(W[k*N+n])
// ---------------------------------------------------------------------------
__global__ __launch_bounds__(256) void transpose_rna(const float* __restrict__ W,
                                                     int N, size_t out_off)
{
    __shared__ float t[32][33];
    const int tx = threadIdx.x, ty = threadIdx.y;
    const int n0 = blockIdx.x * 32, k0 = blockIdx.y * 32;
    #pragma unroll
    for (int i = 0; i < 4; ++i)
        t[ty + i * 8][tx] = W[(size_t)(k0 + ty + i * 8) * N + n0 + tx];
    __syncthreads();
    float* WT = g_WT + out_off;
    #pragma unroll
    for (int i = 0; i < 4; ++i)
        WT[(size_t)(n0 + ty + i * 8) * 1024 + k0 + tx] =
            __uint_as_float(f2tf32(t[tx][ty + i * 8]));
}

// RNA-round x into g_xr (float4 per thread)
__global__ __launch_bounds__(256) void round_x(const float* __restrict__ in)
{
    const size_t i = ((size_t)blockIdx.x * 256 + threadIdx.x) * 4;
    const float4 v = *(const float4*)&in[i];
    uint4 r;
    r.x = f2tf32(v.x); r.y = f2tf32(v.y); r.z = f2tf32(v.z); r.w = f2tf32(v.w);
    *(uint4*)&g_xr[i] = r;
}

// ---------------------------------------------------------------------------
// tf32 mma.sync GEMM: C[128,128] per CTA, K=1024 in 32-wide stages, 3-stage
// cp.async pipeline. 4 warps (2x2), warp tile 64x64 (4 mfrag x 8 nfrag).
// Pointers to scratch resolved IN-KERNEL (device symbols are invalid on host).
// QKV=true : A=g_xr, B=g_WT,          scatter into g_qkv with bias.
// QKV=false: A=g_att, B=g_WT+3M,      write Cout with bias.
// ---------------------------------------------------------------------------
#define STG_BYTES 36864                 // per stage: A 128*36*4 + B same
#define A_FLOATS  4608                  // 18432/4

template<int N, bool QKV>
__global__ __launch_bounds__(128) void gemm_mma(const float* __restrict__ bias,
                                                float* __restrict__ Cout)
{
    extern __shared__ char sm[];
    const float* __restrict__ Aptr = QKV ? g_xr : g_att;
    const float* __restrict__ Bt   = QKV ? g_WT : (g_WT + (size_t)3072 * 1024);

    const int tid  = threadIdx.x;
    const int lane = tid & 31, wid = tid >> 5;
    const int wm   = wid >> 1, wn = wid & 1;
    const int gp   = lane >> 2, tg = lane & 3;
    const int m0   = blockIdx.y * 128, n0 = blockIdx.x * 128;
    const uint32_t smb = smem_u32(sm);

    float d[4][8][4];
    #pragma unroll
    for (int mf = 0; mf < 4; ++mf)
        #pragma unroll
        for (int nf = 0; nf < 8; ++nf)
            #pragma unroll
            for (int q = 0; q < 4; ++q) d[mf][nf][q] = 0.f;

    // loader: f = i*128+tid -> row r=f>>3 (0..127), 16B-chunk kq=f&7
    const int lr = tid >> 3, lkq = tid & 7;

    auto load_stage = [&](int s, int k0) {
        const uint32_t ab = smb + s * STG_BYTES;
        #pragma unroll
        for (int i = 0; i < 8; ++i) {
            const int r = lr + i * 16;
            const uint32_t off = (uint32_t)(r * 36 + lkq * 4) * 4;
            CP_ASYNC16(ab + off,         Aptr + (size_t)(m0 + r) * 1024 + k0 + lkq * 4);
            CP_ASYNC16(ab + 18432 + off, Bt   + (size_t)(n0 + r) * 1024 + k0 + lkq * 4);
        }
    };

    load_stage(0, 0);  CP_COMMIT();
    load_stage(1, 32); CP_COMMIT();

    for (int t = 0; t < 32; ++t) {
        CP_WAIT1();
        __syncthreads();
        if (t + 2 < 32) load_stage((t + 2) % 3, (t + 2) * 32);
        CP_COMMIT();

        const uint32_t* As_ = (const uint32_t*)(sm + (t % 3) * STG_BYTES);
        const uint32_t* Bs_ = As_ + A_FLOATS;

        #pragma unroll
        for (int kk = 0; kk < 32; kk += 8) {
            uint32_t afr[4][4], bfr[8][2];
            #pragma unroll
            for (int mf = 0; mf < 4; ++mf) {
                const int r0 = (wm * 64 + mf * 16 + gp) * 36 + kk + tg;
                afr[mf][0] = As_[r0];
                afr[mf][1] = As_[r0 + 8 * 36];
                afr[mf][2] = As_[r0 + 4];
                afr[mf][3] = As_[r0 + 8 * 36 + 4];
            }
            #pragma unroll
            for (int nf = 0; nf < 8; ++nf) {
                const int c0 = (wn * 64 + nf * 8 + gp) * 36 + kk + tg;
                bfr[nf][0] = Bs_[c0];
                bfr[nf][1] = Bs_[c0 + 4];
            }
            #pragma unroll
            for (int mf = 0; mf < 4; ++mf)
                #pragma unroll
                for (int nf = 0; nf < 8; ++nf)
                    MMA_TF32(d[mf][nf], afr[mf], bfr[nf]);
        }
    }

    // epilogue: c0,c1 at (row, col..col+1); c2,c3 at (row+8, ...)
    #pragma unroll
    for (int mf = 0; mf < 4; ++mf) {
        const int row = m0 + wm * 64 + mf * 16 + gp;
        #pragma unroll
        for (int nf = 0; nf < 8; ++nf) {
            const int col = n0 + wn * 64 + nf * 8 + 2 * tg;
            const float2 bv = *(const float2*)&bias[col];
            #pragma unroll
            for (int h = 0; h < 2; ++h) {
                const int r = row + h * 8;
                float2 v;
                v.x = d[mf][nf][2 * h + 0] + bv.x;
                v.y = d[mf][nf][2 * h + 1] + bv.y;
                if (QKV) {
                    const int which = col >> 10, dd = col & 1023;
                    const int hh = dd >> 6, dk = dd & 63;
                    const int bb = r >> 11, ss = r & 2047;
                    *(float2*)&g_qkv[((size_t)(which * 64 + bb * 16 + hh) * SEQ + ss) * DKH + dk] = v;
                } else {
                    *(float2*)&Cout[(size_t)r * DM + col] = v;
                }
            }
        }
    }
}

// ---------------------------------------------------------------------------
// Causal flash attention, fp32 (epilogue stores tf32-rounded for proj-A)
// ---------------------------------------------------------------------------
__global__ __launch_bounds__(256) void attn_kernel()
{
    extern __shared__ __align__(16) float smbuf[];
    float* Qs  = smbuf;
    float* KPs = smbuf + 64 * 68;
    float* Vs  = smbuf + 2 * 64 * 68;

    const int tid = threadIdx.x;
    const int ty  = tid >> 4;
    const int tx  = tid & 15;
    const int qi  = (int)gridDim.x - 1 - (int)blockIdx.x;
    const int bh  = blockIdx.y;

    const float* Qg = g_qkv + (size_t)(bh)       * (SEQ * DKH);
    const float* Kg = g_qkv + (size_t)(64 + bh)  * (SEQ * DKH);
    const float* Vg = g_qkv + (size_t)(128 + bh) * (SEQ * DKH);

    #pragma unroll
    for (int it = 0; it < 4; ++it) {
        const int f = it * 256 + tid;
        const int r = f >> 4;
        const int c = (f & 15) * 4;
        const float4 q4 = *(const float4*)&Qg[(size_t)(qi * 64 + r) * 64 + c];
        Qs[(c + 0) * 68 + r] = q4.x * 0.125f;
        Qs[(c + 1) * 68 + r] = q4.y * 0.125f;
        Qs[(c + 2) * 68 + r] = q4.z * 0.125f;
        Qs[(c + 3) * 68 + r] = q4.w * 0.125f;
    }

    float m[4], l[4], o[4][4];
    #pragma unroll
    for (int i = 0; i < 4; ++i) {
        m[i] = -1e30f; l[i] = 0.f;
        #pragma unroll
        for (int j = 0; j < 4; ++j) o[i][j] = 0.f;
    }

    for (int j = 0; j <= qi; ++j) {
        #pragma unroll
        for (int it = 0; it < 4; ++it) {
            const int f = it * 256 + tid;
            const int r = f >> 4;
            const int c = (f & 15) * 4;
            const size_t g = (size_t)(j * 64 + r) * 64 + c;
            const float4 k4 = *(const float4*)&Kg[g];
            KPs[(c + 0) * 68 + r] = k4.x;
            KPs[(c + 1) * 68 + r] = k4.y;
            KPs[(c + 2) * 68 + r] = k4.z;
            KPs[(c + 3) * 68 + r] = k4.w;
            *(float4*)&Vs[r * 68 + c] = *(const float4*)&Vg[g];
        }
        __syncthreads();

        float s[4][4];
        #pragma unroll
        for (int i = 0; i < 4; ++i)
            #pragma unroll
            for (int c = 0; c < 4; ++c) s[i][c] = 0.f;
        #pragma unroll 16
        for (int k = 0; k < 64; ++k) {
            const float4 qa = *(const float4*)&Qs [k * 68 + ty * 4];
            const float4 kb = *(const float4*)&KPs[k * 68 + tx * 4];
            const float qv[4] = {qa.x, qa.y, qa.z, qa.w};
            const float kv[4] = {kb.x, kb.y, kb.z, kb.w};
            #pragma unroll
            for (int i = 0; i < 4; ++i)
                #pragma unroll
                for (int c = 0; c < 4; ++c)
                    s[i][c] = fmaf(qv[i], kv[c], s[i][c]);
        }

        if (j == qi) {
            #pragma unroll
            for (int i = 0; i < 4; ++i)
                #pragma unroll
                for (int c = 0; c < 4; ++c)
                    if (tx * 4 + c > ty * 4 + i) s[i][c] = -1e30f;
        }
        __syncthreads();

        #pragma unroll
        for (int i = 0; i < 4; ++i) {
            float mt = fmaxf(fmaxf(s[i][0], s[i][1]), fmaxf(s[i][2], s[i][3]));
            #pragma unroll
            for (int off = 8; off > 0; off >>= 1)
                mt = fmaxf(mt, __shfl_xor_sync(0xffffffffu, mt, off));
            const float mnew = fmaxf(m[i], mt);
            const float corr = __expf(m[i] - mnew);
            float rs = 0.f;
            #pragma unroll
            for (int c = 0; c < 4; ++c) {
                s[i][c] = __expf(s[i][c] - mnew);
                rs += s[i][c];
            }
            #pragma unroll
            for (int off = 8; off > 0; off >>= 1)
                rs += __shfl_xor_sync(0xffffffffu, rs, off);
            l[i] = l[i] * corr + rs;
            m[i] = mnew;
            #pragma unroll
            for (int c = 0; c < 4; ++c) o[i][c] *= corr;
            #pragma unroll
            for (int c = 0; c < 4; ++c)
                KPs[(tx * 4 + c) * 68 + ty * 4 + i] = s[i][c];
        }
        __syncthreads();

        #pragma unroll 16
        for (int k = 0; k < 64; ++k) {
            const float4 p4 = *(const float4*)&KPs[k * 68 + ty * 4];
            const float4 v4 = *(const float4*)&Vs [k * 68 + tx * 4];
            const float pv[4] = {p4.x, p4.y, p4.z, p4.w};
            const float vv[4] = {v4.x, v4.y, v4.z, v4.w};
            #pragma unroll
            for (int i = 0; i < 4; ++i)
                #pragma unroll
                for (int c = 0; c < 4; ++c)
                    o[i][c] = fmaf(pv[i], vv[c], o[i][c]);
        }
        __syncthreads();
    }

    const int bb = bh >> 4, hh = bh & 15;
    #pragma unroll
    for (int i = 0; i < 4; ++i) {
        const float inv = 1.0f / l[i];
        const int srow = qi * 64 + ty * 4 + i;
        uint4 v;   // store tf32-rounded (input to tensor-core proj GEMM)
        v.x = f2tf32(o[i][0] * inv); v.y = f2tf32(o[i][1] * inv);
        v.z = f2tf32(o[i][2] * inv); v.w = f2tf32(o[i][3] * inv);
        *(uint4*)&g_att[((size_t)bb * SEQ + srow) * DM + hh * 64 + tx * 4] = v;
    }
}

// ---------------------------------------------------------------------------
extern "C" void kernel_launch(void* const* d_in, const int* in_sizes, int n_in,
                              void* d_out, int out_size)
{
    const float* x    = (const float*)d_in[0];
    const float* Wqkv = (const float*)d_in[1];
    const float* bqkv = (const float*)d_in[2];
    const float* Wo   = (const float*)d_in[3];
    const float* bo   = (const float*)d_in[4];
    float* out = (float*)d_out;

    // 0) pre-round inputs to tf32 (RNA — avoids HMMA truncation bias)
    transpose_rna<<<dim3(96, 32), dim3(32, 8)>>>(Wqkv, 3072, 0);
    transpose_rna<<<dim3(32, 32), dim3(32, 8)>>>(Wo, 1024, (size_t)3072 * 1024);
    round_x<<<8192, 256>>>(x);

    const int gsm = 3 * STG_BYTES;   // 110592
    cudaFuncSetAttribute(gemm_mma<3072, true>,
                         cudaFuncAttributeMaxDynamicSharedMemorySize, gsm);
    cudaFuncSetAttribute(gemm_mma<1024, false>,
                         cudaFuncAttributeMaxDynamicSharedMemorySize, gsm);

    // 1) QKV projection (tf32 mma.sync) + bias, scatter head-major
    gemm_mma<3072, true><<<dim3(24, 64), 128, gsm>>>(bqkv, nullptr);

    // 2) causal flash attention (fp32 compute, tf32-rounded store)
    const int asm_sz = 3 * 64 * 68 * (int)sizeof(float);
    cudaFuncSetAttribute(attn_kernel, cudaFuncAttributeMaxDynamicSharedMemorySize, asm_sz);
    attn_kernel<<<dim3(32, BATCH * NH), 256, asm_sz>>>();

    // 3) output projection (tf32 mma.sync) + bias
    gemm_mma<1024, false><<<dim3(8, 64), 128, gsm>>>(bo, out);
}